// round 12
// baseline (speedup 1.0000x reference)
#include <cuda_runtime.h>
#include <cuda_fp16.h>
#include <cuda_bf16.h>
#include <math.h>
#include <stdint.h>

// Problem constants
#define N_NODES 16384
#define DIM     128
#define E_MAX   524288
#define ALPHA   0.2f
#define CAP     96        // per-node bucket capacity (Poisson(32) max deg ~60)

// ---------------- scratch (static device globals; no allocation) ----------------
__device__ __half  g_nbrh[N_NODES * DIM];  // nbr features (post-MLP), fp16 gather table
__device__ float   g_acur[N_NODES];        // x_cur . vc + const
__device__ float   g_anbr[N_NODES];        // nbr . wa_bot (fp32)
__device__ __nv_bfloat16 g_Bh[DIM * DIM];  // Wn^T as bf16 hi, layout [n][k]
__device__ __nv_bfloat16 g_Bl[DIM * DIM];  // Wn^T as bf16 lo, layout [n][k]
__device__ float   g_bn[DIM];              // b1n @ W2n + b2n
__device__ float   g_vc[DIM];              // W1c @ (W2c @ wa_top)
__device__ float   g_cconst[1];            // (b1c@W2c+b2c).wa_top + ba
__device__ int     g_counts[N_NODES];
__device__ float2  g_bkt[(size_t)N_NODES * CAP];   // (dst-as-bits, exp) per edge

// ---------------- helpers ----------------
__device__ __forceinline__ uint32_t pack_bf2(float a, float b) {
    __nv_bfloat162 t = __floats2bfloat162_rn(a, b);   // low = a, high = b
    return *(uint32_t*)&t;
}

__device__ __forceinline__ void mma_bf16(float* c, const uint32_t* a, uint32_t b0, uint32_t b1) {
    asm volatile(
        "mma.sync.aligned.m16n8k16.row.col.f32.bf16.bf16.f32 "
        "{%0,%1,%2,%3}, {%4,%5,%6,%7}, {%8,%9}, {%0,%1,%2,%3};"
        : "+f"(c[0]), "+f"(c[1]), "+f"(c[2]), "+f"(c[3])
        : "r"(a[0]), "r"(a[1]), "r"(a[2]), "r"(a[3]), "r"(b0), "r"(b1));
}

// ---------------- kernels ----------------

// prep (merged): blocks 0..127 -> Wn row k=bid (bf16 hi/lo, transposed store);
// 128 -> bn; 129 -> vc/cconst; 130..257 -> zero g_counts.
__global__ void prep_kernel(const float* __restrict__ W1c, const float* __restrict__ b1c,
                            const float* __restrict__ W2c, const float* __restrict__ b2c,
                            const float* __restrict__ W1n, const float* __restrict__ b1n,
                            const float* __restrict__ W2n, const float* __restrict__ b2n,
                            const float* __restrict__ Wa,  const float* __restrict__ ba) {
    int bid = blockIdx.x;
    int t = threadIdx.x;  // 128 threads
    if (bid >= 130) {
        g_counts[(bid - 130) * 128 + t] = 0;
        return;
    }
    if (bid < DIM) {
        __shared__ float row[DIM];
        row[t] = W1n[bid * DIM + t];
        __syncthreads();
        float s = 0.0f;
        #pragma unroll 8
        for (int k = 0; k < DIM; k++) s += row[k] * W2n[k * DIM + t];
        __nv_bfloat16 h = __float2bfloat16_rn(s);
        g_Bh[t * DIM + bid] = h;
        g_Bl[t * DIM + bid] = __float2bfloat16_rn(s - __bfloat162float(h));
    } else if (bid == DIM) {
        float s = b2n[t];
        #pragma unroll 8
        for (int k = 0; k < DIM; k++) s += b1n[k] * W2n[k * DIM + t];
        g_bn[t] = s;
    } else {
        __shared__ float tvec[DIM];
        __shared__ float u[DIM];
        float s = 0.0f;
        #pragma unroll 8
        for (int j = 0; j < DIM; j++) s += W2c[t * DIM + j] * Wa[j];
        tvec[t] = s;
        float su = b2c[t];
        #pragma unroll 8
        for (int k = 0; k < DIM; k++) su += b1c[k] * W2c[k * DIM + t];
        u[t] = su;
        __syncthreads();
        float v = 0.0f;
        #pragma unroll 8
        for (int k = 0; k < DIM; k++) v += W1c[t * DIM + k] * tvec[k];
        g_vc[t] = v;
        if (t == 0) {
            float c = ba[0];
            for (int j = 0; j < DIM; j++) c += u[j] * Wa[j];
            g_cconst[0] = c;
        }
    }
}

// g_acur[i] = x_cur[i,:] . g_vc + g_cconst ; 8 rows per warp
__global__ __launch_bounds__(256) void rowdot_cur_kernel(const float* __restrict__ X) {
    int warp = (blockIdx.x * blockDim.x + threadIdx.x) >> 5;
    int lane = threadIdx.x & 31;
    int base = warp * 8;
    if (base >= N_NODES) return;
    float4 vv = ((const float4*)g_vc)[lane];
    float s[8];
    #pragma unroll
    for (int r = 0; r < 8; r++) {
        float4 x = ((const float4*)(X + (size_t)(base + r) * DIM))[lane];
        s[r] = x.x * vv.x + x.y * vv.y + x.z * vv.z + x.w * vv.w;
    }
    #pragma unroll
    for (int o = 16; o; o >>= 1) {
        #pragma unroll
        for (int r = 0; r < 8; r++) s[r] += __shfl_xor_sync(0xFFFFFFFFu, s[r], o);
    }
    if (lane == 0) {
        float c = g_cconst[0];
        #pragma unroll
        for (int r = 0; r < 8; r++) g_acur[base + r] = s[r] + c;
    }
}

// g_nbrh = fp16(X @ Wn + bn), g_anbr = fp32 row-dots with Wa[D:2D].
// bf16 m16n8k16, 2-way split precision (hi*hi + hi*lo + lo*hi), fp32 acc.
__global__ __launch_bounds__(256) void gemm_tc_kernel(const float* __restrict__ X,
                                                      const float* __restrict__ Wa) {
    __shared__ uint32_t Ah[64][9], Al[64][9];
    __shared__ uint32_t Bh[128][9], Bl[128][9];
    int tid = threadIdx.x;
    int lane = tid & 31, wid = tid >> 5;
    int gid = lane >> 2, tig = lane & 3;
    int wm = wid & 3, wn = wid >> 2;
    int m0 = blockIdx.x * 64;

    const uint32_t* gBh32 = (const uint32_t*)g_Bh;
    const uint32_t* gBl32 = (const uint32_t*)g_Bl;

    float acc[8][4] = {};

    for (int kc = 0; kc < 8; kc++) {
        {
            int r = tid >> 2, j = (tid & 3) * 2;
            float4 v = *(const float4*)&X[(size_t)(m0 + r) * DIM + kc * 16 + j * 2];
            float hx = __bfloat162float(__float2bfloat16_rn(v.x));
            float hy = __bfloat162float(__float2bfloat16_rn(v.y));
            float hz = __bfloat162float(__float2bfloat16_rn(v.z));
            float hw = __bfloat162float(__float2bfloat16_rn(v.w));
            Ah[r][j]     = pack_bf2(hx, hy);
            Ah[r][j + 1] = pack_bf2(hz, hw);
            Al[r][j]     = pack_bf2(v.x - hx, v.y - hy);
            Al[r][j + 1] = pack_bf2(v.z - hz, v.w - hw);
        }
        #pragma unroll
        for (int i = 0; i < 4; i++) {
            int idx = tid + i * 256;
            int n = idx >> 3, kp = idx & 7;
            Bh[n][kp] = gBh32[n * 64 + kc * 8 + kp];
            Bl[n][kp] = gBl32[n * 64 + kc * 8 + kp];
        }
        __syncthreads();

        uint32_t ah[4], al[4];
        int r0 = wm * 16 + gid;
        ah[0] = Ah[r0][tig];     ah[1] = Ah[r0 + 8][tig];
        ah[2] = Ah[r0][tig + 4]; ah[3] = Ah[r0 + 8][tig + 4];
        al[0] = Al[r0][tig];     al[1] = Al[r0 + 8][tig];
        al[2] = Al[r0][tig + 4]; al[3] = Al[r0 + 8][tig + 4];
        #pragma unroll
        for (int nt = 0; nt < 8; nt++) {
            int n = wn * 64 + nt * 8 + gid;
            uint32_t bh0 = Bh[n][tig], bh1 = Bh[n][tig + 4];
            uint32_t bl0 = Bl[n][tig], bl1 = Bl[n][tig + 4];
            mma_bf16(acc[nt], ah, bh0, bh1);
            mma_bf16(acc[nt], al, bh0, bh1);
            mma_bf16(acc[nt], ah, bl0, bl1);
        }
        __syncthreads();
    }

    float* red = (float*)&Ah[0][0];
    int rl0 = wm * 16 + gid;
    int rl1 = rl0 + 8;
    int row0 = m0 + rl0, row1 = m0 + rl1;
    float ad0 = 0.0f, ad1 = 0.0f;
    #pragma unroll
    for (int nt = 0; nt < 8; nt++) {
        int col = wn * 64 + nt * 8 + tig * 2;
        float b0 = g_bn[col], b1 = g_bn[col + 1];
        float w0 = Wa[DIM + col], w1 = Wa[DIM + col + 1];
        float v0 = acc[nt][0] + b0, v1 = acc[nt][1] + b1;
        float v2 = acc[nt][2] + b0, v3 = acc[nt][3] + b1;
        *(__half2*)&g_nbrh[(size_t)row0 * DIM + col] = __floats2half2_rn(v0, v1);
        *(__half2*)&g_nbrh[(size_t)row1 * DIM + col] = __floats2half2_rn(v2, v3);
        ad0 += v0 * w0 + v1 * w1;
        ad1 += v2 * w0 + v3 * w1;
    }
    ad0 += __shfl_xor_sync(0xFFFFFFFFu, ad0, 1);
    ad0 += __shfl_xor_sync(0xFFFFFFFFu, ad0, 2);
    ad1 += __shfl_xor_sync(0xFFFFFFFFu, ad1, 1);
    ad1 += __shfl_xor_sync(0xFFFFFFFFu, ad1, 2);
    if (tig == 0) {
        red[wn * 64 + rl0] = ad0;
        red[wn * 64 + rl1] = ad1;
    }
    __syncthreads();
    if (tid < 64) g_anbr[m0 + tid] = red[tid] + red[64 + tid];
}

// ONE pass over edges: 4 edges per thread, phase-batched for MLP.
// Phase 1: load 4 edges. Phase 2: issue all 8 scattered acur/anbr loads.
// Phase 3: 4 exps. Phase 4: 4 independent atomics. Phase 5: 4 stores.
__global__ __launch_bounds__(256) void score_scatter_kernel(const int* __restrict__ edges, int E) {
    int i = blockIdx.x * blockDim.x + threadIdx.x;
    int base = 4 * i;
    if (base >= E) return;
    int4 eA = ((const int4*)edges)[2 * i];          // edges base, base+1
    int4 eB = ((const int4*)edges)[2 * i + 1];      // edges base+2, base+3
    int s0 = eA.x, d0 = eA.y, s1 = eA.z, d1 = eA.w;
    int s2 = eB.x, d2 = eB.y, s3 = eB.z, d3 = eB.w;
    // batch all scattered loads (8 independent)
    float ac0 = g_acur[s0], an0 = g_anbr[d0];
    float ac1 = g_acur[s1], an1 = g_anbr[d1];
    float ac2 = g_acur[s2], an2 = g_anbr[d2];
    float ac3 = g_acur[s3], an3 = g_anbr[d3];
    float sc0 = ac0 + an0; sc0 = sc0 > 0.0f ? sc0 : ALPHA * sc0;
    float sc1 = ac1 + an1; sc1 = sc1 > 0.0f ? sc1 : ALPHA * sc1;
    float sc2 = ac2 + an2; sc2 = sc2 > 0.0f ? sc2 : ALPHA * sc2;
    float sc3 = ac3 + an3; sc3 = sc3 > 0.0f ? sc3 : ALPHA * sc3;
    float ex0 = __expf(sc0), ex1 = __expf(sc1), ex2 = __expf(sc2), ex3 = __expf(sc3);
    // batch atomics (independent; overlap their latencies)
    int p0 = atomicAdd(&g_counts[s0], 1);
    int p1 = atomicAdd(&g_counts[s1], 1);
    int p2 = atomicAdd(&g_counts[s2], 1);
    int p3 = atomicAdd(&g_counts[s3], 1);
    if (p0 < CAP) g_bkt[(size_t)s0 * CAP + p0] = make_float2(__int_as_float(d0), ex0);
    if (p1 < CAP) g_bkt[(size_t)s1 * CAP + p1] = make_float2(__int_as_float(d1), ex1);
    if (p2 < CAP) g_bkt[(size_t)s2 * CAP + p2] = make_float2(__int_as_float(d2), ex2);
    if (p3 < CAP) g_bkt[(size_t)s3 * CAP + p3] = make_float2(__int_as_float(d3), ex3);
}

// one warp per node; two 16-lane halves gather different edges (LDG.128 each).
__global__ __launch_bounds__(256) void agg_kernel(float* __restrict__ out) {
    int node = blockIdx.x * 8 + (threadIdx.x >> 5);
    int lane = threadIdx.x & 31;
    int half = lane >> 4, li = lane & 15;
    if (node >= N_NODES) return;
    int c = g_counts[node];
    if (c > CAP) c = CAP;
    const float2* bkt = g_bkt + (size_t)node * CAP;
    float acc[8] = {};
    float ssum = 0.0f;
    int p = 0;
    for (; p + 16 <= c; p += 16) {
        float4 q[8];
        #pragma unroll
        for (int j = 0; j < 8; j++) q[j] = ((const float4*)(bkt + p))[j];
        uint4 u[8];
        float w[8];
        #pragma unroll
        for (int j = 0; j < 8; j++) {
            int d = __float_as_int(half ? q[j].z : q[j].x);
            w[j] = half ? q[j].w : q[j].y;
            u[j] = ((const uint4*)(g_nbrh + (size_t)d * DIM))[li];
        }
        #pragma unroll
        for (int j = 0; j < 8; j++) {
            ssum += w[j];
            float2 f0 = __half22float2(*(__half2*)&u[j].x);
            float2 f1 = __half22float2(*(__half2*)&u[j].y);
            float2 f2 = __half22float2(*(__half2*)&u[j].z);
            float2 f3 = __half22float2(*(__half2*)&u[j].w);
            acc[0] += w[j] * f0.x; acc[1] += w[j] * f0.y;
            acc[2] += w[j] * f1.x; acc[3] += w[j] * f1.y;
            acc[4] += w[j] * f2.x; acc[5] += w[j] * f2.y;
            acc[6] += w[j] * f3.x; acc[7] += w[j] * f3.y;
        }
    }
    for (; p < c; p += 2) {
        int e = p + half;
        float2 q = (e < c) ? bkt[e] : make_float2(__int_as_float(0), 0.0f);
        int d = __float_as_int(q.x);
        float wj = q.y;
        uint4 u = ((const uint4*)(g_nbrh + (size_t)d * DIM))[li];
        ssum += wj;
        float2 f0 = __half22float2(*(__half2*)&u.x);
        float2 f1 = __half22float2(*(__half2*)&u.y);
        float2 f2 = __half22float2(*(__half2*)&u.z);
        float2 f3 = __half22float2(*(__half2*)&u.w);
        acc[0] += wj * f0.x; acc[1] += wj * f0.y;
        acc[2] += wj * f1.x; acc[3] += wj * f1.y;
        acc[4] += wj * f2.x; acc[5] += wj * f2.y;
        acc[6] += wj * f3.x; acc[7] += wj * f3.y;
    }
    ssum += __shfl_xor_sync(0xFFFFFFFFu, ssum, 16);
    #pragma unroll
    for (int k = 0; k < 8; k++) acc[k] += __shfl_xor_sync(0xFFFFFFFFu, acc[k], 16);
    if (half == 0) {
        float inv = 1.0f / ssum;
        float* dst = out + (size_t)node * DIM + li * 8;
        ((float4*)dst)[0] = make_float4(acc[0] * inv, acc[1] * inv, acc[2] * inv, acc[3] * inv);
        ((float4*)dst)[1] = make_float4(acc[4] * inv, acc[5] * inv, acc[6] * inv, acc[7] * inv);
    }
}

// ---------------- launch ----------------
extern "C" void kernel_launch(void* const* d_in, const int* in_sizes, int n_in,
                              void* d_out, int out_size) {
    const float* x_cur = (const float*)d_in[0];
    const float* x_nbr = (const float*)d_in[1];
    const float* W1c   = (const float*)d_in[2];
    const float* b1c   = (const float*)d_in[3];
    const float* W2c   = (const float*)d_in[4];
    const float* b2c   = (const float*)d_in[5];
    const float* W1n   = (const float*)d_in[6];
    const float* b1n   = (const float*)d_in[7];
    const float* W2n   = (const float*)d_in[8];
    const float* b2n   = (const float*)d_in[9];
    const float* Wa    = (const float*)d_in[10];
    const float* ba    = (const float*)d_in[11];
    const int*   edges = (const int*)d_in[12];
    float* out = (float*)d_out;

    int E = in_sizes[12] / 2;
    if (E > E_MAX) E = E_MAX;

    prep_kernel<<<258, 128>>>(W1c, b1c, W2c, b2c, W1n, b1n, W2n, b2n, Wa, ba); // 1
    rowdot_cur_kernel<<<N_NODES / 8 / 8, 256>>>(x_cur);                        // 2
    gemm_tc_kernel<<<N_NODES / 64, 256>>>(x_nbr, Wa);                          // 3
    score_scatter_kernel<<<(E / 4 + 255) / 256, 256>>>(edges, E);              // 4 <- profiled
    agg_kernel<<<N_NODES / 8, 256>>>(out);                                     // 5
}

// round 13
// speedup vs baseline: 1.0032x; 1.0032x over previous
#include <cuda_runtime.h>
#include <cuda_fp16.h>
#include <cuda_bf16.h>
#include <math.h>
#include <stdint.h>

// Problem constants
#define N_NODES 16384
#define DIM     128
#define E_MAX   524288
#define ALPHA   0.2f
#define CAP     96        // per-node bucket capacity (Poisson(32) max deg ~60)

// ---------------- scratch (static device globals; no allocation) ----------------
__device__ __half  g_nbrh[N_NODES * DIM];  // nbr features (post-MLP), fp16 gather table
__device__ float   g_acur[N_NODES];        // x_cur . vc + const
__device__ float   g_anbr[N_NODES];        // nbr . wa_bot (fp32)
__device__ __nv_bfloat16 g_Bh[DIM * DIM];  // Wn^T as bf16 hi, layout [n][k]
__device__ __nv_bfloat16 g_Bl[DIM * DIM];  // Wn^T as bf16 lo, layout [n][k]
__device__ float   g_bn[DIM];              // b1n @ W2n + b2n
__device__ float   g_vc[DIM];              // W1c @ (W2c @ wa_top)
__device__ float   g_cconst[1];            // (b1c@W2c+b2c).wa_top + ba
__device__ int     g_counts[N_NODES];
__device__ int     g_bktd[(size_t)N_NODES * CAP];   // dst per edge (score computed in agg)

// ---------------- helpers ----------------
__device__ __forceinline__ uint32_t pack_bf2(float a, float b) {
    __nv_bfloat162 t = __floats2bfloat162_rn(a, b);   // low = a, high = b
    return *(uint32_t*)&t;
}

__device__ __forceinline__ void mma_bf16(float* c, const uint32_t* a, uint32_t b0, uint32_t b1) {
    asm volatile(
        "mma.sync.aligned.m16n8k16.row.col.f32.bf16.bf16.f32 "
        "{%0,%1,%2,%3}, {%4,%5,%6,%7}, {%8,%9}, {%0,%1,%2,%3};"
        : "+f"(c[0]), "+f"(c[1]), "+f"(c[2]), "+f"(c[3])
        : "r"(a[0]), "r"(a[1]), "r"(a[2]), "r"(a[3]), "r"(b0), "r"(b1));
}

// ---------------- kernels ----------------

// prep (merged): blocks 0..127 -> Wn row k=bid (bf16 hi/lo, transposed store);
// 128 -> bn; 129 -> vc/cconst; 130..257 -> zero g_counts.
__global__ void prep_kernel(const float* __restrict__ W1c, const float* __restrict__ b1c,
                            const float* __restrict__ W2c, const float* __restrict__ b2c,
                            const float* __restrict__ W1n, const float* __restrict__ b1n,
                            const float* __restrict__ W2n, const float* __restrict__ b2n,
                            const float* __restrict__ Wa,  const float* __restrict__ ba) {
    int bid = blockIdx.x;
    int t = threadIdx.x;  // 128 threads
    if (bid >= 130) {
        g_counts[(bid - 130) * 128 + t] = 0;
        return;
    }
    if (bid < DIM) {
        __shared__ float row[DIM];
        row[t] = W1n[bid * DIM + t];
        __syncthreads();
        float s = 0.0f;
        #pragma unroll 8
        for (int k = 0; k < DIM; k++) s += row[k] * W2n[k * DIM + t];
        __nv_bfloat16 h = __float2bfloat16_rn(s);
        g_Bh[t * DIM + bid] = h;
        g_Bl[t * DIM + bid] = __float2bfloat16_rn(s - __bfloat162float(h));
    } else if (bid == DIM) {
        float s = b2n[t];
        #pragma unroll 8
        for (int k = 0; k < DIM; k++) s += b1n[k] * W2n[k * DIM + t];
        g_bn[t] = s;
    } else {
        __shared__ float tvec[DIM];
        __shared__ float u[DIM];
        float s = 0.0f;
        #pragma unroll 8
        for (int j = 0; j < DIM; j++) s += W2c[t * DIM + j] * Wa[j];
        tvec[t] = s;
        float su = b2c[t];
        #pragma unroll 8
        for (int k = 0; k < DIM; k++) su += b1c[k] * W2c[k * DIM + t];
        u[t] = su;
        __syncthreads();
        float v = 0.0f;
        #pragma unroll 8
        for (int k = 0; k < DIM; k++) v += W1c[t * DIM + k] * tvec[k];
        g_vc[t] = v;
        if (t == 0) {
            float c = ba[0];
            for (int j = 0; j < DIM; j++) c += u[j] * Wa[j];
            g_cconst[0] = c;
        }
    }
}

// Fused: blocks 0..255 = bf16 tensor-core GEMM (64-row tiles);
// blocks 256..511 = rowdot: g_acur[i] = x_cur[i,:].g_vc + g_cconst (8 rows/warp).
__global__ __launch_bounds__(256) void gemm_fused_kernel(const float* __restrict__ X,
                                                         const float* __restrict__ Xc,
                                                         const float* __restrict__ Wa) {
    __shared__ uint32_t Ah[64][9], Al[64][9];
    __shared__ uint32_t Bh[128][9], Bl[128][9];
    int tid = threadIdx.x;
    int lane = tid & 31, wid = tid >> 5;

    if (blockIdx.x >= 256) {
        // ---- rowdot path ----
        int base = ((blockIdx.x - 256) * 8 + wid) * 8;
        float4 vv = ((const float4*)g_vc)[lane];
        float s[8];
        #pragma unroll
        for (int r = 0; r < 8; r++) {
            float4 x = ((const float4*)(Xc + (size_t)(base + r) * DIM))[lane];
            s[r] = x.x * vv.x + x.y * vv.y + x.z * vv.z + x.w * vv.w;
        }
        #pragma unroll
        for (int o = 16; o; o >>= 1) {
            #pragma unroll
            for (int r = 0; r < 8; r++) s[r] += __shfl_xor_sync(0xFFFFFFFFu, s[r], o);
        }
        if (lane == 0) {
            float c = g_cconst[0];
            #pragma unroll
            for (int r = 0; r < 8; r++) g_acur[base + r] = s[r] + c;
        }
        return;
    }

    // ---- GEMM path ----
    int gid = lane >> 2, tig = lane & 3;
    int wm = wid & 3, wn = wid >> 2;
    int m0 = blockIdx.x * 64;

    const uint32_t* gBh32 = (const uint32_t*)g_Bh;
    const uint32_t* gBl32 = (const uint32_t*)g_Bl;

    float acc[8][4] = {};

    for (int kc = 0; kc < 8; kc++) {
        {
            int r = tid >> 2, j = (tid & 3) * 2;
            float4 v = *(const float4*)&X[(size_t)(m0 + r) * DIM + kc * 16 + j * 2];
            float hx = __bfloat162float(__float2bfloat16_rn(v.x));
            float hy = __bfloat162float(__float2bfloat16_rn(v.y));
            float hz = __bfloat162float(__float2bfloat16_rn(v.z));
            float hw = __bfloat162float(__float2bfloat16_rn(v.w));
            Ah[r][j]     = pack_bf2(hx, hy);
            Ah[r][j + 1] = pack_bf2(hz, hw);
            Al[r][j]     = pack_bf2(v.x - hx, v.y - hy);
            Al[r][j + 1] = pack_bf2(v.z - hz, v.w - hw);
        }
        #pragma unroll
        for (int i = 0; i < 4; i++) {
            int idx = tid + i * 256;
            int n = idx >> 3, kp = idx & 7;
            Bh[n][kp] = gBh32[n * 64 + kc * 8 + kp];
            Bl[n][kp] = gBl32[n * 64 + kc * 8 + kp];
        }
        __syncthreads();

        uint32_t ah[4], al[4];
        int r0 = wm * 16 + gid;
        ah[0] = Ah[r0][tig];     ah[1] = Ah[r0 + 8][tig];
        ah[2] = Ah[r0][tig + 4]; ah[3] = Ah[r0 + 8][tig + 4];
        al[0] = Al[r0][tig];     al[1] = Al[r0 + 8][tig];
        al[2] = Al[r0][tig + 4]; al[3] = Al[r0 + 8][tig + 4];
        #pragma unroll
        for (int nt = 0; nt < 8; nt++) {
            int n = wn * 64 + nt * 8 + gid;
            uint32_t bh0 = Bh[n][tig], bh1 = Bh[n][tig + 4];
            uint32_t bl0 = Bl[n][tig], bl1 = Bl[n][tig + 4];
            mma_bf16(acc[nt], ah, bh0, bh1);
            mma_bf16(acc[nt], al, bh0, bh1);
            mma_bf16(acc[nt], ah, bl0, bl1);
        }
        __syncthreads();
    }

    float* red = (float*)&Ah[0][0];
    int rl0 = wm * 16 + gid;
    int rl1 = rl0 + 8;
    int row0 = m0 + rl0, row1 = m0 + rl1;
    float ad0 = 0.0f, ad1 = 0.0f;
    #pragma unroll
    for (int nt = 0; nt < 8; nt++) {
        int col = wn * 64 + nt * 8 + tig * 2;
        float b0 = g_bn[col], b1 = g_bn[col + 1];
        float w0 = Wa[DIM + col], w1 = Wa[DIM + col + 1];
        float v0 = acc[nt][0] + b0, v1 = acc[nt][1] + b1;
        float v2 = acc[nt][2] + b0, v3 = acc[nt][3] + b1;
        *(__half2*)&g_nbrh[(size_t)row0 * DIM + col] = __floats2half2_rn(v0, v1);
        *(__half2*)&g_nbrh[(size_t)row1 * DIM + col] = __floats2half2_rn(v2, v3);
        ad0 += v0 * w0 + v1 * w1;
        ad1 += v2 * w0 + v3 * w1;
    }
    ad0 += __shfl_xor_sync(0xFFFFFFFFu, ad0, 1);
    ad0 += __shfl_xor_sync(0xFFFFFFFFu, ad0, 2);
    ad1 += __shfl_xor_sync(0xFFFFFFFFu, ad1, 1);
    ad1 += __shfl_xor_sync(0xFFFFFFFFu, ad1, 2);
    if (tig == 0) {
        red[wn * 64 + rl0] = ad0;
        red[wn * 64 + rl1] = ad1;
    }
    __syncthreads();
    if (tid < 64) g_anbr[m0 + tid] = red[tid] + red[64 + tid];
}

// Scatter only: per edge, atomic slot + 4B dst store. No float math, no
// scattered float loads (score computed in agg). 2 edges/thread via int4.
__global__ void scatter_kernel(const int* __restrict__ edges, int E) {
    int i = blockIdx.x * blockDim.x + threadIdx.x;
    int e0 = 2 * i;
    if (e0 >= E) return;
    int4 ed = ((const int4*)edges)[i];
    int p0 = atomicAdd(&g_counts[ed.x], 1);
    if (p0 < CAP) g_bktd[(size_t)ed.x * CAP + p0] = ed.y;
    if (e0 + 1 < E) {
        int p1 = atomicAdd(&g_counts[ed.z], 1);
        if (p1 < CAP) g_bktd[(size_t)ed.z * CAP + p1] = ed.w;
    }
}

// one warp per node; two 16-lane halves gather different edges (LDG.128 each).
// Weight computed in-kernel: w = exp(leaky(acur[node] + anbr[dst])).
// anbr[dst] is loaded broadcast-within-half (1 sector per half).
__global__ __launch_bounds__(256) void agg_kernel(float* __restrict__ out) {
    int node = blockIdx.x * 8 + (threadIdx.x >> 5);
    int lane = threadIdx.x & 31;
    int half = lane >> 4, li = lane & 15;
    if (node >= N_NODES) return;
    int c = g_counts[node];
    if (c > CAP) c = CAP;
    float acn = g_acur[node];
    const int* bkt = g_bktd + (size_t)node * CAP;
    float acc[8] = {};
    float ssum = 0.0f;
    int p = 0;
    for (; p + 16 <= c; p += 16) {
        int4 b[4];
        #pragma unroll
        for (int k = 0; k < 4; k++) b[k] = ((const int4*)(bkt + p))[k];
        // half0 -> edges p+2j, half1 -> p+2j+1
        int dd[8];
        #pragma unroll
        for (int j = 0; j < 8; j++) {
            int4 bb = b[j >> 1];
            dd[j] = (j & 1) ? (half ? bb.w : bb.z) : (half ? bb.y : bb.x);
        }
        // issue all row gathers, then all anbr loads (broadcast per half)
        uint4 u[8];
        #pragma unroll
        for (int j = 0; j < 8; j++) u[j] = ((const uint4*)(g_nbrh + (size_t)dd[j] * DIM))[li];
        float an[8];
        #pragma unroll
        for (int j = 0; j < 8; j++) an[j] = g_anbr[dd[j]];
        #pragma unroll
        for (int j = 0; j < 8; j++) {
            float sc = acn + an[j];
            sc = sc > 0.0f ? sc : ALPHA * sc;
            float w = __expf(sc);
            ssum += w;
            float2 f0 = __half22float2(*(__half2*)&u[j].x);
            float2 f1 = __half22float2(*(__half2*)&u[j].y);
            float2 f2 = __half22float2(*(__half2*)&u[j].z);
            float2 f3 = __half22float2(*(__half2*)&u[j].w);
            acc[0] += w * f0.x; acc[1] += w * f0.y;
            acc[2] += w * f1.x; acc[3] += w * f1.y;
            acc[4] += w * f2.x; acc[5] += w * f2.y;
            acc[6] += w * f3.x; acc[7] += w * f3.y;
        }
    }
    for (; p < c; p += 2) {
        int e = p + half;
        bool act = e < c;
        int d = act ? bkt[e] : 0;
        uint4 u = ((const uint4*)(g_nbrh + (size_t)d * DIM))[li];
        float w = 0.0f;
        if (act) {
            float sc = acn + g_anbr[d];
            sc = sc > 0.0f ? sc : ALPHA * sc;
            w = __expf(sc);
        }
        ssum += w;
        float2 f0 = __half22float2(*(__half2*)&u.x);
        float2 f1 = __half22float2(*(__half2*)&u.y);
        float2 f2 = __half22float2(*(__half2*)&u.z);
        float2 f3 = __half22float2(*(__half2*)&u.w);
        acc[0] += w * f0.x; acc[1] += w * f0.y;
        acc[2] += w * f1.x; acc[3] += w * f1.y;
        acc[4] += w * f2.x; acc[5] += w * f2.y;
        acc[6] += w * f3.x; acc[7] += w * f3.y;
    }
    ssum += __shfl_xor_sync(0xFFFFFFFFu, ssum, 16);
    #pragma unroll
    for (int k = 0; k < 8; k++) acc[k] += __shfl_xor_sync(0xFFFFFFFFu, acc[k], 16);
    if (half == 0) {
        float inv = 1.0f / ssum;
        float* dst = out + (size_t)node * DIM + li * 8;
        ((float4*)dst)[0] = make_float4(acc[0] * inv, acc[1] * inv, acc[2] * inv, acc[3] * inv);
        ((float4*)dst)[1] = make_float4(acc[4] * inv, acc[5] * inv, acc[6] * inv, acc[7] * inv);
    }
}

// ---------------- launch ----------------
extern "C" void kernel_launch(void* const* d_in, const int* in_sizes, int n_in,
                              void* d_out, int out_size) {
    const float* x_cur = (const float*)d_in[0];
    const float* x_nbr = (const float*)d_in[1];
    const float* W1c   = (const float*)d_in[2];
    const float* b1c   = (const float*)d_in[3];
    const float* W2c   = (const float*)d_in[4];
    const float* b2c   = (const float*)d_in[5];
    const float* W1n   = (const float*)d_in[6];
    const float* b1n   = (const float*)d_in[7];
    const float* W2n   = (const float*)d_in[8];
    const float* b2n   = (const float*)d_in[9];
    const float* Wa    = (const float*)d_in[10];
    const float* ba    = (const float*)d_in[11];
    const int*   edges = (const int*)d_in[12];
    float* out = (float*)d_out;

    int E = in_sizes[12] / 2;
    if (E > E_MAX) E = E_MAX;

    prep_kernel<<<258, 128>>>(W1c, b1c, W2c, b2c, W1n, b1n, W2n, b2n, Wa, ba); // 1
    gemm_fused_kernel<<<512, 256>>>(x_nbr, x_cur, Wa);                         // 2 (gemm + rowdot)
    scatter_kernel<<<(E / 2 + 255) / 256, 256>>>(edges, E);                    // 3
    agg_kernel<<<N_NODES / 8, 256>>>(out);                                     // 4 <- profiled
}

// round 14
// speedup vs baseline: 1.1017x; 1.0982x over previous
#include <cuda_runtime.h>
#include <cuda_fp16.h>
#include <cuda_bf16.h>
#include <math.h>
#include <stdint.h>

// Problem constants
#define N_NODES 16384
#define DIM     128
#define E_MAX   524288
#define ALPHA   0.2f
#define CAP     96        // per-node bucket capacity (Poisson(32) max deg ~60)

// ---------------- scratch (static device globals; no allocation) ----------------
__device__ __half  g_nbrh[N_NODES * DIM];  // nbr features (post-MLP), fp16 gather table
__device__ float   g_acur[N_NODES];        // x_cur . vc + const
__device__ float   g_anbr[N_NODES];        // nbr . wa_bot (fp32)
__device__ __nv_bfloat16 g_Bh[DIM * DIM];  // Wn^T as bf16 hi, layout [n][k]
__device__ __nv_bfloat16 g_Bl[DIM * DIM];  // Wn^T as bf16 lo, layout [n][k]
__device__ float   g_bn[DIM];              // b1n @ W2n + b2n
__device__ float   g_vc[DIM];              // W1c @ (W2c @ wa_top)
__device__ float   g_cconst[1];            // (b1c@W2c+b2c).wa_top + ba
__device__ int     g_counts[N_NODES];
__device__ int     g_bktd[(size_t)N_NODES * CAP];   // dst per edge

// ---------------- helpers ----------------
__device__ __forceinline__ uint32_t pack_bf2(float a, float b) {
    __nv_bfloat162 t = __floats2bfloat162_rn(a, b);   // low = a, high = b
    return *(uint32_t*)&t;
}

__device__ __forceinline__ void mma_bf16(float* c, const uint32_t* a, uint32_t b0, uint32_t b1) {
    asm volatile(
        "mma.sync.aligned.m16n8k16.row.col.f32.bf16.bf16.f32 "
        "{%0,%1,%2,%3}, {%4,%5,%6,%7}, {%8,%9}, {%0,%1,%2,%3};"
        : "+f"(c[0]), "+f"(c[1]), "+f"(c[2]), "+f"(c[3])
        : "r"(a[0]), "r"(a[1]), "r"(a[2]), "r"(a[3]), "r"(b0), "r"(b1));
}

// ---------------- kernels ----------------

// prep (merged): blocks 0..127 -> Wn row k=bid (bf16 hi/lo, transposed store);
// 128 -> bn; 129 -> vc/cconst; 130..257 -> zero g_counts.
__global__ void prep_kernel(const float* __restrict__ W1c, const float* __restrict__ b1c,
                            const float* __restrict__ W2c, const float* __restrict__ b2c,
                            const float* __restrict__ W1n, const float* __restrict__ b1n,
                            const float* __restrict__ W2n, const float* __restrict__ b2n,
                            const float* __restrict__ Wa,  const float* __restrict__ ba) {
    int bid = blockIdx.x;
    int t = threadIdx.x;  // 128 threads
    if (bid >= 130) {
        g_counts[(bid - 130) * 128 + t] = 0;
        return;
    }
    if (bid < DIM) {
        __shared__ float row[DIM];
        row[t] = W1n[bid * DIM + t];
        __syncthreads();
        float s = 0.0f;
        #pragma unroll 8
        for (int k = 0; k < DIM; k++) s += row[k] * W2n[k * DIM + t];
        __nv_bfloat16 h = __float2bfloat16_rn(s);
        g_Bh[t * DIM + bid] = h;
        g_Bl[t * DIM + bid] = __float2bfloat16_rn(s - __bfloat162float(h));
    } else if (bid == DIM) {
        float s = b2n[t];
        #pragma unroll 8
        for (int k = 0; k < DIM; k++) s += b1n[k] * W2n[k * DIM + t];
        g_bn[t] = s;
    } else {
        __shared__ float tvec[DIM];
        __shared__ float u[DIM];
        float s = 0.0f;
        #pragma unroll 8
        for (int j = 0; j < DIM; j++) s += W2c[t * DIM + j] * Wa[j];
        tvec[t] = s;
        float su = b2c[t];
        #pragma unroll 8
        for (int k = 0; k < DIM; k++) su += b1c[k] * W2c[k * DIM + t];
        u[t] = su;
        __syncthreads();
        float v = 0.0f;
        #pragma unroll 8
        for (int k = 0; k < DIM; k++) v += W1c[t * DIM + k] * tvec[k];
        g_vc[t] = v;
        if (t == 0) {
            float c = ba[0];
            for (int j = 0; j < DIM; j++) c += u[j] * Wa[j];
            g_cconst[0] = c;
        }
    }
}

// Scatter only: per edge, atomic slot + 4B dst store. 2 edges/thread via int4.
__global__ void scatter_kernel(const int* __restrict__ edges, int E) {
    int i = blockIdx.x * blockDim.x + threadIdx.x;
    int e0 = 2 * i;
    if (e0 >= E) return;
    int4 ed = ((const int4*)edges)[i];
    int p0 = atomicAdd(&g_counts[ed.x], 1);
    if (p0 < CAP) g_bktd[(size_t)ed.x * CAP + p0] = ed.y;
    if (e0 + 1 < E) {
        int p1 = atomicAdd(&g_counts[ed.z], 1);
        if (p1 < CAP) g_bktd[(size_t)ed.z * CAP + p1] = ed.w;
    }
}

// g_acur[i] = x_cur[i,:] . g_vc + g_cconst ; 8 rows per warp
__global__ __launch_bounds__(256) void rowdot_cur_kernel(const float* __restrict__ X) {
    int warp = (blockIdx.x * blockDim.x + threadIdx.x) >> 5;
    int lane = threadIdx.x & 31;
    int base = warp * 8;
    if (base >= N_NODES) return;
    float4 vv = ((const float4*)g_vc)[lane];
    float s[8];
    #pragma unroll
    for (int r = 0; r < 8; r++) {
        float4 x = ((const float4*)(X + (size_t)(base + r) * DIM))[lane];
        s[r] = x.x * vv.x + x.y * vv.y + x.z * vv.z + x.w * vv.w;
    }
    #pragma unroll
    for (int o = 16; o; o >>= 1) {
        #pragma unroll
        for (int r = 0; r < 8; r++) s[r] += __shfl_xor_sync(0xFFFFFFFFu, s[r], o);
    }
    if (lane == 0) {
        float c = g_cconst[0];
        #pragma unroll
        for (int r = 0; r < 8; r++) g_acur[base + r] = s[r] + c;
    }
}

// g_nbrh = fp16(X @ Wn + bn), g_anbr = fp32 row-dots with Wa[D:2D].
// bf16 m16n8k16, split-precision (hi*hi + lo*hi + hi*lo), fp32 acc.
// Single-stage: full A tile + full B in 104KB dynamic smem, ONE sync, then
// an uninterrupted MMA stream (no inter-chunk barriers).
// 256 blocks x 64-row tiles; 8 warps: 4(m) x 2(n). Strides padded to 68
// words so fragment-read bank = lane (conflict-free).
#define AS 68
__global__ __launch_bounds__(256) void gemm_tc_kernel(const float* __restrict__ X,
                                                      const float* __restrict__ Wa) {
    extern __shared__ uint32_t sm[];
    uint32_t* Ah = sm;                 // [64][68]
    uint32_t* Al = sm + 64 * AS;       // [64][68]
    uint32_t* Bh = sm + 2 * 64 * AS;   // [128][68]
    uint32_t* Bl = Bh + 128 * AS;      // [128][68]
    int tid = threadIdx.x;
    int lane = tid & 31, wid = tid >> 5;
    int gid = lane >> 2, tig = lane & 3;
    int wm = wid & 3, wn = wid >> 2;
    int m0 = blockIdx.x * 64;

    const uint4* gBh4 = (const uint4*)g_Bh;   // [128][16 uint4]
    const uint4* gBl4 = (const uint4*)g_Bl;

    // stage A: 64 rows x 128 floats = 2048 float4, 8/thread; split hi/lo
    #pragma unroll
    for (int i = 0; i < 8; i++) {
        int idx = tid + i * 256;               // 0..2047
        int r = idx >> 5, c4 = (idx & 31) * 4; // float col
        float4 v = *(const float4*)&X[(size_t)(m0 + r) * DIM + c4];
        int j = c4 >> 1;                       // pair index
        float hx = __bfloat162float(__float2bfloat16_rn(v.x));
        float hy = __bfloat162float(__float2bfloat16_rn(v.y));
        float hz = __bfloat162float(__float2bfloat16_rn(v.z));
        float hw = __bfloat162float(__float2bfloat16_rn(v.w));
        Ah[r * AS + j]     = pack_bf2(hx, hy);
        Ah[r * AS + j + 1] = pack_bf2(hz, hw);
        Al[r * AS + j]     = pack_bf2(v.x - hx, v.y - hy);
        Al[r * AS + j + 1] = pack_bf2(v.z - hz, v.w - hw);
    }
    // stage B: 128 n x 64 pairs (hi+lo), uint4 = 4 pairs; 2048 uint4 each, 8/thread
    #pragma unroll
    for (int i = 0; i < 8; i++) {
        int idx = tid + i * 256;               // 0..2047
        int n = idx >> 4, q = idx & 15;        // q-th uint4 of row n
        *(uint4*)&Bh[n * AS + q * 4] = gBh4[n * 16 + q];
        *(uint4*)&Bl[n * AS + q * 4] = gBl4[n * 16 + q];
    }
    __syncthreads();

    float acc[8][4] = {};
    int r0 = wm * 16 + gid;
    #pragma unroll
    for (int kk = 0; kk < 8; kk++) {           // 8 chunks of K=16, no barriers
        int kb = kk * 8;
        uint32_t ah[4], al[4];
        ah[0] = Ah[r0 * AS + kb + tig];       ah[1] = Ah[(r0 + 8) * AS + kb + tig];
        ah[2] = Ah[r0 * AS + kb + tig + 4];   ah[3] = Ah[(r0 + 8) * AS + kb + tig + 4];
        al[0] = Al[r0 * AS + kb + tig];       al[1] = Al[(r0 + 8) * AS + kb + tig];
        al[2] = Al[r0 * AS + kb + tig + 4];   al[3] = Al[(r0 + 8) * AS + kb + tig + 4];
        #pragma unroll
        for (int nt = 0; nt < 8; nt++) {
            int n = wn * 64 + nt * 8 + gid;
            uint32_t bh0 = Bh[n * AS + kb + tig], bh1 = Bh[n * AS + kb + tig + 4];
            uint32_t bl0 = Bl[n * AS + kb + tig], bl1 = Bl[n * AS + kb + tig + 4];
            mma_bf16(acc[nt], ah, bh0, bh1);
            mma_bf16(acc[nt], al, bh0, bh1);
            mma_bf16(acc[nt], ah, bl0, bl1);
        }
    }
    __syncthreads();

    // epilogue: + bias, fp16 store, fused partial a_nbr per wn-half (fp32)
    float* red = (float*)sm;
    int rl0 = wm * 16 + gid;
    int rl1 = rl0 + 8;
    int row0 = m0 + rl0, row1 = m0 + rl1;
    float ad0 = 0.0f, ad1 = 0.0f;
    #pragma unroll
    for (int nt = 0; nt < 8; nt++) {
        int col = wn * 64 + nt * 8 + tig * 2;
        float b0 = g_bn[col], b1 = g_bn[col + 1];
        float w0 = Wa[DIM + col], w1 = Wa[DIM + col + 1];
        float v0 = acc[nt][0] + b0, v1 = acc[nt][1] + b1;
        float v2 = acc[nt][2] + b0, v3 = acc[nt][3] + b1;
        *(__half2*)&g_nbrh[(size_t)row0 * DIM + col] = __floats2half2_rn(v0, v1);
        *(__half2*)&g_nbrh[(size_t)row1 * DIM + col] = __floats2half2_rn(v2, v3);
        ad0 += v0 * w0 + v1 * w1;
        ad1 += v2 * w0 + v3 * w1;
    }
    ad0 += __shfl_xor_sync(0xFFFFFFFFu, ad0, 1);
    ad0 += __shfl_xor_sync(0xFFFFFFFFu, ad0, 2);
    ad1 += __shfl_xor_sync(0xFFFFFFFFu, ad1, 1);
    ad1 += __shfl_xor_sync(0xFFFFFFFFu, ad1, 2);
    if (tig == 0) {
        red[wn * 64 + rl0] = ad0;
        red[wn * 64 + rl1] = ad1;
    }
    __syncthreads();
    if (tid < 64) g_anbr[m0 + tid] = red[tid] + red[64 + tid];
}
#define GEMM_SMEM ((2 * 64 * AS + 2 * 128 * AS) * 4)

// one warp per node; two 16-lane halves gather different edges (LDG.128 each).
// Weight computed in-kernel: w = exp(leaky(acur[node] + anbr[dst])).
__global__ __launch_bounds__(256) void agg_kernel(float* __restrict__ out) {
    int node = blockIdx.x * 8 + (threadIdx.x >> 5);
    int lane = threadIdx.x & 31;
    int half = lane >> 4, li = lane & 15;
    if (node >= N_NODES) return;
    int c = g_counts[node];
    if (c > CAP) c = CAP;
    float acn = g_acur[node];
    const int* bkt = g_bktd + (size_t)node * CAP;
    float acc[8] = {};
    float ssum = 0.0f;
    int p = 0;
    for (; p + 16 <= c; p += 16) {
        int4 b[4];
        #pragma unroll
        for (int k = 0; k < 4; k++) b[k] = ((const int4*)(bkt + p))[k];
        int dd[8];
        #pragma unroll
        for (int j = 0; j < 8; j++) {
            int4 bb = b[j >> 1];
            dd[j] = (j & 1) ? (half ? bb.w : bb.z) : (half ? bb.y : bb.x);
        }
        uint4 u[8];
        #pragma unroll
        for (int j = 0; j < 8; j++) u[j] = ((const uint4*)(g_nbrh + (size_t)dd[j] * DIM))[li];
        float an[8];
        #pragma unroll
        for (int j = 0; j < 8; j++) an[j] = g_anbr[dd[j]];
        #pragma unroll
        for (int j = 0; j < 8; j++) {
            float sc = acn + an[j];
            sc = sc > 0.0f ? sc : ALPHA * sc;
            float w = __expf(sc);
            ssum += w;
            float2 f0 = __half22float2(*(__half2*)&u[j].x);
            float2 f1 = __half22float2(*(__half2*)&u[j].y);
            float2 f2 = __half22float2(*(__half2*)&u[j].z);
            float2 f3 = __half22float2(*(__half2*)&u[j].w);
            acc[0] += w * f0.x; acc[1] += w * f0.y;
            acc[2] += w * f1.x; acc[3] += w * f1.y;
            acc[4] += w * f2.x; acc[5] += w * f2.y;
            acc[6] += w * f3.x; acc[7] += w * f3.y;
        }
    }
    for (; p < c; p += 2) {
        int e = p + half;
        bool act = e < c;
        int d = act ? bkt[e] : 0;
        uint4 u = ((const uint4*)(g_nbrh + (size_t)d * DIM))[li];
        float w = 0.0f;
        if (act) {
            float sc = acn + g_anbr[d];
            sc = sc > 0.0f ? sc : ALPHA * sc;
            w = __expf(sc);
        }
        ssum += w;
        float2 f0 = __half22float2(*(__half2*)&u.x);
        float2 f1 = __half22float2(*(__half2*)&u.y);
        float2 f2 = __half22float2(*(__half2*)&u.z);
        float2 f3 = __half22float2(*(__half2*)&u.w);
        acc[0] += w * f0.x; acc[1] += w * f0.y;
        acc[2] += w * f1.x; acc[3] += w * f1.y;
        acc[4] += w * f2.x; acc[5] += w * f2.y;
        acc[6] += w * f3.x; acc[7] += w * f3.y;
    }
    ssum += __shfl_xor_sync(0xFFFFFFFFu, ssum, 16);
    #pragma unroll
    for (int k = 0; k < 8; k++) acc[k] += __shfl_xor_sync(0xFFFFFFFFu, acc[k], 16);
    if (half == 0) {
        float inv = 1.0f / ssum;
        float* dst = out + (size_t)node * DIM + li * 8;
        ((float4*)dst)[0] = make_float4(acc[0] * inv, acc[1] * inv, acc[2] * inv, acc[3] * inv);
        ((float4*)dst)[1] = make_float4(acc[4] * inv, acc[5] * inv, acc[6] * inv, acc[7] * inv);
    }
}

// ---------------- launch ----------------
extern "C" void kernel_launch(void* const* d_in, const int* in_sizes, int n_in,
                              void* d_out, int out_size) {
    const float* x_cur = (const float*)d_in[0];
    const float* x_nbr = (const float*)d_in[1];
    const float* W1c   = (const float*)d_in[2];
    const float* b1c   = (const float*)d_in[3];
    const float* W2c   = (const float*)d_in[4];
    const float* b2c   = (const float*)d_in[5];
    const float* W1n   = (const float*)d_in[6];
    const float* b1n   = (const float*)d_in[7];
    const float* W2n   = (const float*)d_in[8];
    const float* b2n   = (const float*)d_in[9];
    const float* Wa    = (const float*)d_in[10];
    const float* ba    = (const float*)d_in[11];
    const int*   edges = (const int*)d_in[12];
    float* out = (float*)d_out;

    int E = in_sizes[12] / 2;
    if (E > E_MAX) E = E_MAX;

    static bool attr_set = false;
    if (!attr_set) {
        cudaFuncSetAttribute(gemm_tc_kernel,
                             cudaFuncAttributeMaxDynamicSharedMemorySize, GEMM_SMEM);
        attr_set = true;
    }

    prep_kernel<<<258, 128>>>(W1c, b1c, W2c, b2c, W1n, b1n, W2n, b2n, Wa, ba); // 1
    scatter_kernel<<<(E / 2 + 255) / 256, 256>>>(edges, E);                    // 2
    rowdot_cur_kernel<<<N_NODES / 8 / 8, 256>>>(x_cur);                        // 3
    gemm_tc_kernel<<<N_NODES / 64, 256, GEMM_SMEM>>>(x_nbr, Wa);               // 4 <- profiled
    agg_kernel<<<N_NODES / 8, 256>>>(out);                                     // 5
}

// round 15
// speedup vs baseline: 1.1568x; 1.0500x over previous
#include <cuda_runtime.h>
#include <cuda_fp16.h>
#include <cuda_bf16.h>
#include <math.h>
#include <stdint.h>

// Problem constants
#define N_NODES 16384
#define DIM     128
#define E_MAX   524288
#define ALPHA   0.2f
#define CAP     96        // per-node bucket capacity (Poisson(32) max deg ~60)

// ---------------- scratch (static device globals; no allocation) ----------------
__device__ __half  g_nbrh[N_NODES * DIM];  // nbr features (post-MLP), fp16 gather table
__device__ float   g_anbr[N_NODES];        // nbr . wa_bot (fp32)
__device__ __nv_bfloat16 g_Bh[DIM * DIM];  // Wn^T as bf16 hi, layout [n][k]
__device__ __nv_bfloat16 g_Bl[DIM * DIM];  // Wn^T as bf16 lo, layout [n][k]
__device__ float   g_bn[DIM];              // b1n @ W2n + b2n
__device__ float   g_vc[DIM];              // W1c @ (W2c @ wa_top)
__device__ float   g_cconst[1];            // (b1c@W2c+b2c).wa_top + ba
__device__ int     g_counts[N_NODES];
__device__ int     g_bktd[(size_t)N_NODES * CAP];   // dst per edge

// ---------------- helpers ----------------
__device__ __forceinline__ uint32_t pack_bf2(float a, float b) {
    __nv_bfloat162 t = __floats2bfloat162_rn(a, b);   // low = a, high = b
    return *(uint32_t*)&t;
}

__device__ __forceinline__ void mma_bf16(float* c, const uint32_t* a, uint32_t b0, uint32_t b1) {
    asm volatile(
        "mma.sync.aligned.m16n8k16.row.col.f32.bf16.bf16.f32 "
        "{%0,%1,%2,%3}, {%4,%5,%6,%7}, {%8,%9}, {%0,%1,%2,%3};"
        : "+f"(c[0]), "+f"(c[1]), "+f"(c[2]), "+f"(c[3])
        : "r"(a[0]), "r"(a[1]), "r"(a[2]), "r"(a[3]), "r"(b0), "r"(b1));
}

// ---------------- kernels ----------------

// prep (merged): blocks 0..127 -> Wn row k=bid (bf16 hi/lo, transposed store);
// 128 -> bn; 129 -> vc/cconst; 130..257 -> zero g_counts.
__global__ void prep_kernel(const float* __restrict__ W1c, const float* __restrict__ b1c,
                            const float* __restrict__ W2c, const float* __restrict__ b2c,
                            const float* __restrict__ W1n, const float* __restrict__ b1n,
                            const float* __restrict__ W2n, const float* __restrict__ b2n,
                            const float* __restrict__ Wa,  const float* __restrict__ ba) {
    int bid = blockIdx.x;
    int t = threadIdx.x;  // 128 threads
    if (bid >= 130) {
        g_counts[(bid - 130) * 128 + t] = 0;
        return;
    }
    if (bid < DIM) {
        __shared__ float row[DIM];
        row[t] = W1n[bid * DIM + t];
        __syncthreads();
        float s = 0.0f;
        #pragma unroll 8
        for (int k = 0; k < DIM; k++) s += row[k] * W2n[k * DIM + t];
        __nv_bfloat16 h = __float2bfloat16_rn(s);
        g_Bh[t * DIM + bid] = h;
        g_Bl[t * DIM + bid] = __float2bfloat16_rn(s - __bfloat162float(h));
    } else if (bid == DIM) {
        float s = b2n[t];
        #pragma unroll 8
        for (int k = 0; k < DIM; k++) s += b1n[k] * W2n[k * DIM + t];
        g_bn[t] = s;
    } else {
        __shared__ float tvec[DIM];
        __shared__ float u[DIM];
        float s = 0.0f;
        #pragma unroll 8
        for (int j = 0; j < DIM; j++) s += W2c[t * DIM + j] * Wa[j];
        tvec[t] = s;
        float su = b2c[t];
        #pragma unroll 8
        for (int k = 0; k < DIM; k++) su += b1c[k] * W2c[k * DIM + t];
        u[t] = su;
        __syncthreads();
        float v = 0.0f;
        #pragma unroll 8
        for (int k = 0; k < DIM; k++) v += W1c[t * DIM + k] * tvec[k];
        g_vc[t] = v;
        if (t == 0) {
            float c = ba[0];
            for (int j = 0; j < DIM; j++) c += u[j] * Wa[j];
            g_cconst[0] = c;
        }
    }
}

// Scatter only: per edge, atomic slot + 4B dst store. 2 edges/thread via int4.
__global__ void scatter_kernel(const int* __restrict__ edges, int E) {
    int i = blockIdx.x * blockDim.x + threadIdx.x;
    int e0 = 2 * i;
    if (e0 >= E) return;
    int4 ed = ((const int4*)edges)[i];
    int p0 = atomicAdd(&g_counts[ed.x], 1);
    if (p0 < CAP) g_bktd[(size_t)ed.x * CAP + p0] = ed.y;
    if (e0 + 1 < E) {
        int p1 = atomicAdd(&g_counts[ed.z], 1);
        if (p1 < CAP) g_bktd[(size_t)ed.z * CAP + p1] = ed.w;
    }
}

// g_nbrh = fp16(X @ Wn + bn), g_anbr = fp32 row-dots with Wa[D:2D].
// bf16 m16n8k16, split-precision (hi*hi + lo*hi + hi*lo), fp32 acc.
// Single-stage: full A tile + full B in 104KB dynamic smem, ONE sync, then
// an uninterrupted MMA stream. 256 blocks x 64-row tiles; 8 warps 4(m)x2(n).
#define AS 68
__global__ __launch_bounds__(256) void gemm_tc_kernel(const float* __restrict__ X,
                                                      const float* __restrict__ Wa) {
    extern __shared__ uint32_t sm[];
    uint32_t* Ah = sm;                 // [64][68]
    uint32_t* Al = sm + 64 * AS;       // [64][68]
    uint32_t* Bh = sm + 2 * 64 * AS;   // [128][68]
    uint32_t* Bl = Bh + 128 * AS;      // [128][68]
    int tid = threadIdx.x;
    int lane = tid & 31, wid = tid >> 5;
    int gid = lane >> 2, tig = lane & 3;
    int wm = wid & 3, wn = wid >> 2;
    int m0 = blockIdx.x * 64;

    const uint4* gBh4 = (const uint4*)g_Bh;   // [128][16 uint4]
    const uint4* gBl4 = (const uint4*)g_Bl;

    #pragma unroll
    for (int i = 0; i < 8; i++) {
        int idx = tid + i * 256;               // 0..2047
        int r = idx >> 5, c4 = (idx & 31) * 4;
        float4 v = *(const float4*)&X[(size_t)(m0 + r) * DIM + c4];
        int j = c4 >> 1;
        float hx = __bfloat162float(__float2bfloat16_rn(v.x));
        float hy = __bfloat162float(__float2bfloat16_rn(v.y));
        float hz = __bfloat162float(__float2bfloat16_rn(v.z));
        float hw = __bfloat162float(__float2bfloat16_rn(v.w));
        Ah[r * AS + j]     = pack_bf2(hx, hy);
        Ah[r * AS + j + 1] = pack_bf2(hz, hw);
        Al[r * AS + j]     = pack_bf2(v.x - hx, v.y - hy);
        Al[r * AS + j + 1] = pack_bf2(v.z - hz, v.w - hw);
    }
    #pragma unroll
    for (int i = 0; i < 8; i++) {
        int idx = tid + i * 256;               // 0..2047
        int n = idx >> 4, q = idx & 15;
        *(uint4*)&Bh[n * AS + q * 4] = gBh4[n * 16 + q];
        *(uint4*)&Bl[n * AS + q * 4] = gBl4[n * 16 + q];
    }
    __syncthreads();

    float acc[8][4] = {};
    int r0 = wm * 16 + gid;
    #pragma unroll
    for (int kk = 0; kk < 8; kk++) {
        int kb = kk * 8;
        uint32_t ah[4], al[4];
        ah[0] = Ah[r0 * AS + kb + tig];       ah[1] = Ah[(r0 + 8) * AS + kb + tig];
        ah[2] = Ah[r0 * AS + kb + tig + 4];   ah[3] = Ah[(r0 + 8) * AS + kb + tig + 4];
        al[0] = Al[r0 * AS + kb + tig];       al[1] = Al[(r0 + 8) * AS + kb + tig];
        al[2] = Al[r0 * AS + kb + tig + 4];   al[3] = Al[(r0 + 8) * AS + kb + tig + 4];
        #pragma unroll
        for (int nt = 0; nt < 8; nt++) {
            int n = wn * 64 + nt * 8 + gid;
            uint32_t bh0 = Bh[n * AS + kb + tig], bh1 = Bh[n * AS + kb + tig + 4];
            uint32_t bl0 = Bl[n * AS + kb + tig], bl1 = Bl[n * AS + kb + tig + 4];
            mma_bf16(acc[nt], ah, bh0, bh1);
            mma_bf16(acc[nt], al, bh0, bh1);
            mma_bf16(acc[nt], ah, bl0, bl1);
        }
    }
    __syncthreads();

    float* red = (float*)sm;
    int rl0 = wm * 16 + gid;
    int rl1 = rl0 + 8;
    int row0 = m0 + rl0, row1 = m0 + rl1;
    float ad0 = 0.0f, ad1 = 0.0f;
    #pragma unroll
    for (int nt = 0; nt < 8; nt++) {
        int col = wn * 64 + nt * 8 + tig * 2;
        float b0 = g_bn[col], b1 = g_bn[col + 1];
        float w0 = Wa[DIM + col], w1 = Wa[DIM + col + 1];
        float v0 = acc[nt][0] + b0, v1 = acc[nt][1] + b1;
        float v2 = acc[nt][2] + b0, v3 = acc[nt][3] + b1;
        *(__half2*)&g_nbrh[(size_t)row0 * DIM + col] = __floats2half2_rn(v0, v1);
        *(__half2*)&g_nbrh[(size_t)row1 * DIM + col] = __floats2half2_rn(v2, v3);
        ad0 += v0 * w0 + v1 * w1;
        ad1 += v2 * w0 + v3 * w1;
    }
    ad0 += __shfl_xor_sync(0xFFFFFFFFu, ad0, 1);
    ad0 += __shfl_xor_sync(0xFFFFFFFFu, ad0, 2);
    ad1 += __shfl_xor_sync(0xFFFFFFFFu, ad1, 1);
    ad1 += __shfl_xor_sync(0xFFFFFFFFu, ad1, 2);
    if (tig == 0) {
        red[wn * 64 + rl0] = ad0;
        red[wn * 64 + rl1] = ad1;
    }
    __syncthreads();
    if (tid < 64) g_anbr[m0 + tid] = red[tid] + red[64 + tid];
}
#define GEMM_SMEM ((2 * 64 * AS + 2 * 128 * AS) * 4)

// one warp per node; computes acur[node] inline (x_cur row . g_vc + cconst),
// then two 16-lane halves gather different edges (LDG.128 each), with
// w = exp(leaky(acur + anbr[dst])) computed on the fly.
__global__ __launch_bounds__(256) void agg_kernel(const float* __restrict__ Xc,
                                                  float* __restrict__ out) {
    int node = blockIdx.x * 8 + (threadIdx.x >> 5);
    int lane = threadIdx.x & 31;
    int half = lane >> 4, li = lane & 15;
    if (node >= N_NODES) return;
    // inline acur: one 512B row load + warp reduce (latency hidden under buckets)
    float4 xr = ((const float4*)(Xc + (size_t)node * DIM))[lane];
    float4 vv = ((const float4*)g_vc)[lane];
    float acn = xr.x * vv.x + xr.y * vv.y + xr.z * vv.z + xr.w * vv.w;
    int c = g_counts[node];
    if (c > CAP) c = CAP;
    const int* bkt = g_bktd + (size_t)node * CAP;
    #pragma unroll
    for (int o = 16; o; o >>= 1) acn += __shfl_xor_sync(0xFFFFFFFFu, acn, o);
    acn += g_cconst[0];

    float acc[8] = {};
    float ssum = 0.0f;
    int p = 0;
    for (; p + 16 <= c; p += 16) {
        int4 b[4];
        #pragma unroll
        for (int k = 0; k < 4; k++) b[k] = ((const int4*)(bkt + p))[k];
        int dd[8];
        #pragma unroll
        for (int j = 0; j < 8; j++) {
            int4 bb = b[j >> 1];
            dd[j] = (j & 1) ? (half ? bb.w : bb.z) : (half ? bb.y : bb.x);
        }
        uint4 u[8];
        #pragma unroll
        for (int j = 0; j < 8; j++) u[j] = ((const uint4*)(g_nbrh + (size_t)dd[j] * DIM))[li];
        float an[8];
        #pragma unroll
        for (int j = 0; j < 8; j++) an[j] = g_anbr[dd[j]];
        #pragma unroll
        for (int j = 0; j < 8; j++) {
            float sc = acn + an[j];
            sc = sc > 0.0f ? sc : ALPHA * sc;
            float w = __expf(sc);
            ssum += w;
            float2 f0 = __half22float2(*(__half2*)&u[j].x);
            float2 f1 = __half22float2(*(__half2*)&u[j].y);
            float2 f2 = __half22float2(*(__half2*)&u[j].z);
            float2 f3 = __half22float2(*(__half2*)&u[j].w);
            acc[0] += w * f0.x; acc[1] += w * f0.y;
            acc[2] += w * f1.x; acc[3] += w * f1.y;
            acc[4] += w * f2.x; acc[5] += w * f2.y;
            acc[6] += w * f3.x; acc[7] += w * f3.y;
        }
    }
    for (; p < c; p += 2) {
        int e = p + half;
        bool act = e < c;
        int d = act ? bkt[e] : 0;
        uint4 u = ((const uint4*)(g_nbrh + (size_t)d * DIM))[li];
        float w = 0.0f;
        if (act) {
            float sc = acn + g_anbr[d];
            sc = sc > 0.0f ? sc : ALPHA * sc;
            w = __expf(sc);
        }
        ssum += w;
        float2 f0 = __half22float2(*(__half2*)&u.x);
        float2 f1 = __half22float2(*(__half2*)&u.y);
        float2 f2 = __half22float2(*(__half2*)&u.z);
        float2 f3 = __half22float2(*(__half2*)&u.w);
        acc[0] += w * f0.x; acc[1] += w * f0.y;
        acc[2] += w * f1.x; acc[3] += w * f1.y;
        acc[4] += w * f2.x; acc[5] += w * f2.y;
        acc[6] += w * f3.x; acc[7] += w * f3.y;
    }
    ssum += __shfl_xor_sync(0xFFFFFFFFu, ssum, 16);
    #pragma unroll
    for (int k = 0; k < 8; k++) acc[k] += __shfl_xor_sync(0xFFFFFFFFu, acc[k], 16);
    if (half == 0) {
        float inv = 1.0f / ssum;
        float* dst = out + (size_t)node * DIM + li * 8;
        ((float4*)dst)[0] = make_float4(acc[0] * inv, acc[1] * inv, acc[2] * inv, acc[3] * inv);
        ((float4*)dst)[1] = make_float4(acc[4] * inv, acc[5] * inv, acc[6] * inv, acc[7] * inv);
    }
}

// ---------------- launch ----------------
extern "C" void kernel_launch(void* const* d_in, const int* in_sizes, int n_in,
                              void* d_out, int out_size) {
    const float* x_cur = (const float*)d_in[0];
    const float* x_nbr = (const float*)d_in[1];
    const float* W1c   = (const float*)d_in[2];
    const float* b1c   = (const float*)d_in[3];
    const float* W2c   = (const float*)d_in[4];
    const float* b2c   = (const float*)d_in[5];
    const float* W1n   = (const float*)d_in[6];
    const float* b1n   = (const float*)d_in[7];
    const float* W2n   = (const float*)d_in[8];
    const float* b2n   = (const float*)d_in[9];
    const float* Wa    = (const float*)d_in[10];
    const float* ba    = (const float*)d_in[11];
    const int*   edges = (const int*)d_in[12];
    float* out = (float*)d_out;

    int E = in_sizes[12] / 2;
    if (E > E_MAX) E = E_MAX;

    static bool attr_set = false;
    if (!attr_set) {
        cudaFuncSetAttribute(gemm_tc_kernel,
                             cudaFuncAttributeMaxDynamicSharedMemorySize, GEMM_SMEM);
        attr_set = true;
    }

    prep_kernel<<<258, 128>>>(W1c, b1c, W2c, b2c, W1n, b1n, W2n, b2n, Wa, ba); // 1
    scatter_kernel<<<(E / 2 + 255) / 256, 256>>>(edges, E);                    // 2
    gemm_tc_kernel<<<N_NODES / 64, 256, GEMM_SMEM>>>(x_nbr, Wa);               // 3
    agg_kernel<<<N_NODES / 8, 256>>>(x_cur, out);                              // 4 <- profiled
}

// round 16
// speedup vs baseline: 1.2163x; 1.0514x over previous
#include <cuda_runtime.h>
#include <cuda_fp16.h>
#include <math.h>
#include <stdint.h>

// Problem constants
#define N_NODES 16384
#define DIM     128
#define E_MAX   524288
#define ALPHA   0.2f
#define CAP     96        // per-node bucket capacity (Poisson(32) max deg ~60)

// ---------------- scratch (static device globals; no allocation) ----------------
__device__ __half  g_nbrh[N_NODES * DIM];  // nbr features (post-MLP), fp16 gather table
__device__ float   g_anbr[N_NODES];        // nbr . wa_bot (fp32)
__device__ __half  g_Wh[DIM * DIM];        // Wn^T as fp16, layout [n][k]
__device__ float   g_bn[DIM];              // b1n @ W2n + b2n
__device__ float   g_vc[DIM];              // W1c @ (W2c @ wa_top)
__device__ float   g_cconst[1];            // (b1c@W2c+b2c).wa_top + ba
__device__ int     g_counts[N_NODES];
__device__ int     g_bktd[(size_t)N_NODES * CAP];   // dst per edge

// ---------------- helpers ----------------
__device__ __forceinline__ void mma_f16(float* c, const uint32_t* a, uint32_t b0, uint32_t b1) {
    asm volatile(
        "mma.sync.aligned.m16n8k16.row.col.f32.f16.f16.f32 "
        "{%0,%1,%2,%3}, {%4,%5,%6,%7}, {%8,%9}, {%0,%1,%2,%3};"
        : "+f"(c[0]), "+f"(c[1]), "+f"(c[2]), "+f"(c[3])
        : "r"(a[0]), "r"(a[1]), "r"(a[2]), "r"(a[3]), "r"(b0), "r"(b1));
}

// ---------------- kernels ----------------

// prep (merged): blocks 0..127 -> Wn row k=bid (fp16, transposed store);
// 128 -> bn; 129 -> vc/cconst; 130..257 -> zero g_counts.
__global__ void prep_kernel(const float* __restrict__ W1c, const float* __restrict__ b1c,
                            const float* __restrict__ W2c, const float* __restrict__ b2c,
                            const float* __restrict__ W1n, const float* __restrict__ b1n,
                            const float* __restrict__ W2n, const float* __restrict__ b2n,
                            const float* __restrict__ Wa,  const float* __restrict__ ba) {
    int bid = blockIdx.x;
    int t = threadIdx.x;  // 128 threads
    if (bid >= 130) {
        g_counts[(bid - 130) * 128 + t] = 0;
        return;
    }
    if (bid < DIM) {
        __shared__ float row[DIM];
        row[t] = W1n[bid * DIM + t];
        __syncthreads();
        float s = 0.0f;
        #pragma unroll 8
        for (int k = 0; k < DIM; k++) s += row[k] * W2n[k * DIM + t];
        g_Wh[t * DIM + bid] = __float2half_rn(s);   // transposed [n][k]
    } else if (bid == DIM) {
        float s = b2n[t];
        #pragma unroll 8
        for (int k = 0; k < DIM; k++) s += b1n[k] * W2n[k * DIM + t];
        g_bn[t] = s;
    } else {
        __shared__ float tvec[DIM];
        __shared__ float u[DIM];
        float s = 0.0f;
        #pragma unroll 8
        for (int j = 0; j < DIM; j++) s += W2c[t * DIM + j] * Wa[j];
        tvec[t] = s;
        float su = b2c[t];
        #pragma unroll 8
        for (int k = 0; k < DIM; k++) su += b1c[k] * W2c[k * DIM + t];
        u[t] = su;
        __syncthreads();
        float v = 0.0f;
        #pragma unroll 8
        for (int k = 0; k < DIM; k++) v += W1c[t * DIM + k] * tvec[k];
        g_vc[t] = v;
        if (t == 0) {
            float c = ba[0];
            for (int j = 0; j < DIM; j++) c += u[j] * Wa[j];
            g_cconst[0] = c;
        }
    }
}

// Fused launch: blocks 0..255 = fp16 tensor-core GEMM (64-row tiles);
// blocks 256.. = edge scatter (atomic slot + 4B dst store, 2 edges/thread).
// Both depend only on prep; overlap in one wave.
// GEMM: fp16 m16n8k16 single-term, fp32 acc. Full A tile + full B in 51KB
// dynamic smem, ONE sync, uninterrupted MMA stream. 8 warps 4(m)x2(n).
#define AS 68
__global__ __launch_bounds__(256) void gemm_scatter_kernel(const float* __restrict__ X,
                                                           const float* __restrict__ Wa,
                                                           const int* __restrict__ edges, int E) {
    extern __shared__ uint32_t sm[];
    int tid = threadIdx.x;

    if (blockIdx.x >= 256) {
        // ---- scatter path ----
        int i = (blockIdx.x - 256) * 256 + tid;
        int e0 = 2 * i;
        if (e0 >= E) return;
        int4 ed = ((const int4*)edges)[i];
        int p0 = atomicAdd(&g_counts[ed.x], 1);
        if (p0 < CAP) g_bktd[(size_t)ed.x * CAP + p0] = ed.y;
        if (e0 + 1 < E) {
            int p1 = atomicAdd(&g_counts[ed.z], 1);
            if (p1 < CAP) g_bktd[(size_t)ed.z * CAP + p1] = ed.w;
        }
        return;
    }

    // ---- GEMM path ----
    uint32_t* Ah = sm;                 // [64][68] half2 pairs
    uint32_t* Bh = sm + 64 * AS;       // [128][68]
    int lane = tid & 31, wid = tid >> 5;
    int gid = lane >> 2, tig = lane & 3;
    int wm = wid & 3, wn = wid >> 2;
    int m0 = blockIdx.x * 64;

    const uint4* gWh4 = (const uint4*)g_Wh;   // [128][16 uint4]

    // stage A: 64 rows x 128 floats = 2048 float4, 8/thread; cvt to half2
    #pragma unroll
    for (int i = 0; i < 8; i++) {
        int idx = tid + i * 256;               // 0..2047
        int r = idx >> 5, c4 = (idx & 31) * 4;
        float4 v = *(const float4*)&X[(size_t)(m0 + r) * DIM + c4];
        int j = c4 >> 1;
        __half2 p0 = __floats2half2_rn(v.x, v.y);
        __half2 p1 = __floats2half2_rn(v.z, v.w);
        Ah[r * AS + j]     = *(uint32_t*)&p0;
        Ah[r * AS + j + 1] = *(uint32_t*)&p1;
    }
    // stage B: 128 n-rows x 64 pairs; uint4 = 4 pairs; 2048 uint4, 8/thread
    #pragma unroll
    for (int i = 0; i < 8; i++) {
        int idx = tid + i * 256;               // 0..2047
        int n = idx >> 4, q = idx & 15;
        *(uint4*)&Bh[n * AS + q * 4] = gWh4[n * 16 + q];
    }
    __syncthreads();

    float acc[8][4] = {};
    int r0 = wm * 16 + gid;
    #pragma unroll
    for (int kk = 0; kk < 8; kk++) {           // 8 chunks of K=16, no barriers
        int kb = kk * 8;
        uint32_t ah[4];
        ah[0] = Ah[r0 * AS + kb + tig];       ah[1] = Ah[(r0 + 8) * AS + kb + tig];
        ah[2] = Ah[r0 * AS + kb + tig + 4];   ah[3] = Ah[(r0 + 8) * AS + kb + tig + 4];
        #pragma unroll
        for (int nt = 0; nt < 8; nt++) {
            int n = wn * 64 + nt * 8 + gid;
            uint32_t b0 = Bh[n * AS + kb + tig], b1 = Bh[n * AS + kb + tig + 4];
            mma_f16(acc[nt], ah, b0, b1);
        }
    }
    __syncthreads();

    // epilogue: + bias, fp16 store, fused partial a_nbr per wn-half (fp32)
    float* red = (float*)sm;
    int rl0 = wm * 16 + gid;
    int rl1 = rl0 + 8;
    int row0 = m0 + rl0, row1 = m0 + rl1;
    float ad0 = 0.0f, ad1 = 0.0f;
    #pragma unroll
    for (int nt = 0; nt < 8; nt++) {
        int col = wn * 64 + nt * 8 + tig * 2;
        float b0 = g_bn[col], b1 = g_bn[col + 1];
        float w0 = Wa[DIM + col], w1 = Wa[DIM + col + 1];
        float v0 = acc[nt][0] + b0, v1 = acc[nt][1] + b1;
        float v2 = acc[nt][2] + b0, v3 = acc[nt][3] + b1;
        *(__half2*)&g_nbrh[(size_t)row0 * DIM + col] = __floats2half2_rn(v0, v1);
        *(__half2*)&g_nbrh[(size_t)row1 * DIM + col] = __floats2half2_rn(v2, v3);
        ad0 += v0 * w0 + v1 * w1;
        ad1 += v2 * w0 + v3 * w1;
    }
    ad0 += __shfl_xor_sync(0xFFFFFFFFu, ad0, 1);
    ad0 += __shfl_xor_sync(0xFFFFFFFFu, ad0, 2);
    ad1 += __shfl_xor_sync(0xFFFFFFFFu, ad1, 1);
    ad1 += __shfl_xor_sync(0xFFFFFFFFu, ad1, 2);
    if (tig == 0) {
        red[wn * 64 + rl0] = ad0;
        red[wn * 64 + rl1] = ad1;
    }
    __syncthreads();
    if (tid < 64) g_anbr[m0 + tid] = red[tid] + red[64 + tid];
}
#define GEMM_SMEM ((64 * AS + 128 * AS) * 4)

// one warp per node; computes acur[node] inline (x_cur row . g_vc + cconst),
// then two 16-lane halves gather different edges (LDG.128 each), with
// w = exp(leaky(acur + anbr[dst])) computed on the fly.
__global__ __launch_bounds__(256) void agg_kernel(const float* __restrict__ Xc,
                                                  float* __restrict__ out) {
    int node = blockIdx.x * 8 + (threadIdx.x >> 5);
    int lane = threadIdx.x & 31;
    int half = lane >> 4, li = lane & 15;
    if (node >= N_NODES) return;
    float4 xr = ((const float4*)(Xc + (size_t)node * DIM))[lane];
    float4 vv = ((const float4*)g_vc)[lane];
    float acn = xr.x * vv.x + xr.y * vv.y + xr.z * vv.z + xr.w * vv.w;
    int c = g_counts[node];
    if (c > CAP) c = CAP;
    const int* bkt = g_bktd + (size_t)node * CAP;
    #pragma unroll
    for (int o = 16; o; o >>= 1) acn += __shfl_xor_sync(0xFFFFFFFFu, acn, o);
    acn += g_cconst[0];

    float acc[8] = {};
    float ssum = 0.0f;
    int p = 0;
    for (; p + 16 <= c; p += 16) {
        int4 b[4];
        #pragma unroll
        for (int k = 0; k < 4; k++) b[k] = ((const int4*)(bkt + p))[k];
        int dd[8];
        #pragma unroll
        for (int j = 0; j < 8; j++) {
            int4 bb = b[j >> 1];
            dd[j] = (j & 1) ? (half ? bb.w : bb.z) : (half ? bb.y : bb.x);
        }
        uint4 u[8];
        #pragma unroll
        for (int j = 0; j < 8; j++) u[j] = ((const uint4*)(g_nbrh + (size_t)dd[j] * DIM))[li];
        float an[8];
        #pragma unroll
        for (int j = 0; j < 8; j++) an[j] = g_anbr[dd[j]];
        #pragma unroll
        for (int j = 0; j < 8; j++) {
            float sc = acn + an[j];
            sc = sc > 0.0f ? sc : ALPHA * sc;
            float w = __expf(sc);
            ssum += w;
            float2 f0 = __half22float2(*(__half2*)&u[j].x);
            float2 f1 = __half22float2(*(__half2*)&u[j].y);
            float2 f2 = __half22float2(*(__half2*)&u[j].z);
            float2 f3 = __half22float2(*(__half2*)&u[j].w);
            acc[0] += w * f0.x; acc[1] += w * f0.y;
            acc[2] += w * f1.x; acc[3] += w * f1.y;
            acc[4] += w * f2.x; acc[5] += w * f2.y;
            acc[6] += w * f3.x; acc[7] += w * f3.y;
        }
    }
    for (; p < c; p += 2) {
        int e = p + half;
        bool act = e < c;
        int d = act ? bkt[e] : 0;
        uint4 u = ((const uint4*)(g_nbrh + (size_t)d * DIM))[li];
        float w = 0.0f;
        if (act) {
            float sc = acn + g_anbr[d];
            sc = sc > 0.0f ? sc : ALPHA * sc;
            w = __expf(sc);
        }
        ssum += w;
        float2 f0 = __half22float2(*(__half2*)&u.x);
        float2 f1 = __half22float2(*(__half2*)&u.y);
        float2 f2 = __half22float2(*(__half2*)&u.z);
        float2 f3 = __half22float2(*(__half2*)&u.w);
        acc[0] += w * f0.x; acc[1] += w * f0.y;
        acc[2] += w * f1.x; acc[3] += w * f1.y;
        acc[4] += w * f2.x; acc[5] += w * f2.y;
        acc[6] += w * f3.x; acc[7] += w * f3.y;
    }
    ssum += __shfl_xor_sync(0xFFFFFFFFu, ssum, 16);
    #pragma unroll
    for (int k = 0; k < 8; k++) acc[k] += __shfl_xor_sync(0xFFFFFFFFu, acc[k], 16);
    if (half == 0) {
        float inv = 1.0f / ssum;
        float* dst = out + (size_t)node * DIM + li * 8;
        ((float4*)dst)[0] = make_float4(acc[0] * inv, acc[1] * inv, acc[2] * inv, acc[3] * inv);
        ((float4*)dst)[1] = make_float4(acc[4] * inv, acc[5] * inv, acc[6] * inv, acc[7] * inv);
    }
}

// ---------------- launch ----------------
extern "C" void kernel_launch(void* const* d_in, const int* in_sizes, int n_in,
                              void* d_out, int out_size) {
    const float* x_cur = (const float*)d_in[0];
    const float* x_nbr = (const float*)d_in[1];
    const float* W1c   = (const float*)d_in[2];
    const float* b1c   = (const float*)d_in[3];
    const float* W2c   = (const float*)d_in[4];
    const float* b2c   = (const float*)d_in[5];
    const float* W1n   = (const float*)d_in[6];
    const float* b1n   = (const float*)d_in[7];
    const float* W2n   = (const float*)d_in[8];
    const float* b2n   = (const float*)d_in[9];
    const float* Wa    = (const float*)d_in[10];
    const float* ba    = (const float*)d_in[11];
    const int*   edges = (const int*)d_in[12];
    float* out = (float*)d_out;

    int E = in_sizes[12] / 2;
    if (E > E_MAX) E = E_MAX;

    static bool attr_set = false;
    if (!attr_set) {
        cudaFuncSetAttribute(gemm_scatter_kernel,
                             cudaFuncAttributeMaxDynamicSharedMemorySize, GEMM_SMEM);
        attr_set = true;
    }

    int scatter_blocks = (E / 2 + 255) / 256;
    prep_kernel<<<258, 128>>>(W1c, b1c, W2c, b2c, W1n, b1n, W2n, b2n, Wa, ba);        // 1
    gemm_scatter_kernel<<<256 + scatter_blocks, 256, GEMM_SMEM>>>(x_nbr, Wa, edges, E); // 2
    agg_kernel<<<N_NODES / 8, 256>>>(x_cur, out);                                       // 3
}